// round 2
// baseline (speedup 1.0000x reference)
#include <cuda_runtime.h>
#include <math.h>

#define BB   4
#define TT0  128
#define WD   128
#define EB   16
#define LL   2048
#define ODIM 24
#define TF   122

// ---------------- scratch (no allocations allowed) ----------------
__device__ float g_bufA[BB*WD*TT0*EB];   // 4 MB
__device__ float g_bufB[BB*WD*TT0*EB];   // 4 MB
__device__ float g_Mt[2*WD*WD];          // Mt[m*128+n] = (Wq Wk^T)[n][m]
__device__ float g_uu[2*WD];             // u = Wq bk
__device__ float g_ww[2*WD];             // w = Wk bq
__device__ float g_cc[2];                // c = bq . bk
__device__ float g_yv[BB*126*WD];        // per-(b,t) y vectors

// ---------------- embed: x_in -> (B,N,T,E) ----------------
__global__ void k_embed(const float* __restrict__ x_in,
                        const float* __restrict__ emb_w,
                        const float* __restrict__ emb_b,
                        float* __restrict__ out) {
    int idx = blockIdx.x*blockDim.x + threadIdx.x;   // over B*T*N
    if (idx >= BB*TT0*WD) return;
    int n = idx & 127;
    int t = (idx >> 7) & 127;
    int b = idx >> 14;
    const float* xi = x_in + (b*TT0 + t)*131;
    float v  = xi[n];
    float f0 = xi[128], f1 = xi[129], f2 = xi[130];
    float* o = out + ((b*WD + n)*TT0 + t)*EB;
    #pragma unroll
    for (int e = 0; e < EB; e++)
        o[e] = v*emb_w[e] + f0*emb_w[16+e] + f1*emb_w[32+e] + f2*emb_w[48+e] + emb_b[e];
}

// ---------------- precompute Mt[m*128+n] = sum_l Wq[n,l]*Wk[m,l] ----------------
__global__ void k_mt(const float* __restrict__ Wq, const float* __restrict__ Wk,
                     float* __restrict__ Mt) {
    __shared__ float Aq[16][65], Ak[16][65];
    int bm = blockIdx.x >> 3, bn = blockIdx.x & 7;
    int m0 = bm*16, n0 = bn*16;
    int ty = threadIdx.x >> 4, tx = threadIdx.x & 15;  // ty -> m, tx -> n
    float acc = 0.f;
    for (int l0 = 0; l0 < LL; l0 += 64) {
        #pragma unroll
        for (int r = 0; r < 4; r++) {
            int idx = threadIdx.x + r*256;
            int row = idx >> 6, col = idx & 63;
            Aq[row][col] = Wq[(n0+row)*LL + l0 + col];
            Ak[row][col] = Wk[(m0+row)*LL + l0 + col];
        }
        __syncthreads();
        #pragma unroll
        for (int lc = 0; lc < 64; lc++)
            acc += Ak[ty][lc]*Aq[tx][lc];
        __syncthreads();
    }
    Mt[(m0+ty)*WD + (n0+tx)] = acc;
}

// ---------------- precompute u, w, c ----------------
__global__ void k_uw(const float* __restrict__ Wq, const float* __restrict__ Wk,
                     const float* __restrict__ bq, const float* __restrict__ bk,
                     float* __restrict__ u, float* __restrict__ w, float* __restrict__ cp) {
    int n = blockIdx.x;
    __shared__ float su[256], sw[256], sc[256];
    float pu = 0.f, pw = 0.f, pc = 0.f;
    for (int l = threadIdx.x; l < LL; l += 256) {
        float bkl = bk[l], bql = bq[l];
        pu += Wq[n*LL + l]*bkl;
        pw += Wk[n*LL + l]*bql;
        if (n == 0) pc += bql*bkl;
    }
    su[threadIdx.x] = pu; sw[threadIdx.x] = pw; sc[threadIdx.x] = pc;
    __syncthreads();
    for (int s = 128; s > 0; s >>= 1) {
        if (threadIdx.x < s) {
            su[threadIdx.x] += su[threadIdx.x + s];
            sw[threadIdx.x] += sw[threadIdx.x + s];
            sc[threadIdx.x] += sc[threadIdx.x + s];
        }
        __syncthreads();
    }
    if (threadIdx.x == 0) {
        u[n] = su[0]; w[n] = sw[0];
        if (n == 0) *cp = sc[0];
    }
}

// ---------------- gated conv: Y = tanh(f)*sigmoid(g) ----------------
// f[b,o,t,e] = sum_i wf[o,i,0]*X[b,i,t,e] + wf[o,i,1]*X[b,i,t+D,e] + bf[o]
template<int TIN, int TOUT, int D, int TT>
__global__ void k_gated_fg(const float* __restrict__ X,
                           const float* __restrict__ wf, const float* __restrict__ bf,
                           const float* __restrict__ wg, const float* __restrict__ bg,
                           float* __restrict__ Y) {
    const int WIDTH = TT + D;
    extern __shared__ float Xs[];  // [128][WIDTH][16]
    const int ntile = (TOUT + TT - 1)/TT;
    int b  = blockIdx.x / ntile;
    int t0 = (blockIdx.x % ntile)*TT;
    // load X[b, i, t0..t0+WIDTH-1, e]
    for (int idx = threadIdx.x; idx < WD*WIDTH*EB; idx += blockDim.x) {
        int e = idx & 15;
        int w = (idx >> 4) % WIDTH;
        int i = idx / (16*WIDTH);
        int t = t0 + w;
        Xs[idx] = (t < TIN) ? X[((b*WD + i)*TIN + t)*EB + e] : 0.f;
    }
    __syncthreads();
    for (int p = threadIdx.x; p < WD*EB; p += blockDim.x) {
        int o = p >> 4, e = p & 15;
        float fa[TT], ga[TT];
        #pragma unroll
        for (int j = 0; j < TT; j++) { fa[j] = 0.f; ga[j] = 0.f; }
        const float* wfo = wf + o*WD*2;
        const float* wgo = wg + o*WD*2;
        for (int i = 0; i < WD; i++) {
            float wf0 = wfo[i*2], wf1 = wfo[i*2+1];
            float wg0 = wgo[i*2], wg1 = wgo[i*2+1];
            const float* xr = Xs + (i*WIDTH)*16 + e;
            #pragma unroll
            for (int j = 0; j < TT; j++) {
                float x0 = xr[j*16];
                float x1 = xr[(j+D)*16];
                fa[j] += wf0*x0 + wf1*x1;
                ga[j] += wg0*x0 + wg1*x1;
            }
        }
        float bfo = bf[o], bgo = bg[o];
        #pragma unroll
        for (int j = 0; j < TT; j++) {
            int t = t0 + j;
            if (t < TOUT) {
                float fv = tanhf(fa[j] + bfo);
                float sv = 1.f/(1.f + expf(-(ga[j] + bgo)));
                Y[((b*WD + o)*TOUT + t)*EB + e] = fv*sv;
            }
        }
    }
}

// ---------------- gated residual: Y += X @ ws + bs (over time) ----------------
template<int TIN, int TOUT>
__global__ void k_gated_res(const float* __restrict__ X, const float* __restrict__ ws,
                            const float* __restrict__ bs, float* __restrict__ Y) {
    __shared__ float Xs[TIN*EB];
    int b = blockIdx.x >> 7, n = blockIdx.x & 127;
    const float* xp = X + (size_t)(b*WD + n)*TIN*EB;
    for (int idx = threadIdx.x; idx < TIN*EB; idx += blockDim.x) Xs[idx] = xp[idx];
    __syncthreads();
    float* yp = Y + (size_t)(b*WD + n)*TOUT*EB;
    for (int idx = threadIdx.x; idx < TOUT*EB; idx += blockDim.x) {
        int s = idx >> 4, e = idx & 15;
        float acc = bs[s];
        for (int t = 0; t < TIN; t++)
            acc += Xs[t*16 + e]*ws[t*TOUT + s];
        yp[idx] += acc;
    }
}

// ---------------- attention scores -> y[b,t,n] ----------------
template<int T>
__global__ void k_attn_scores(const float* __restrict__ X, const float* __restrict__ Mt,
                              const float* __restrict__ u, const float* __restrict__ w,
                              const float* __restrict__ cptr, float* __restrict__ yout) {
    __shared__ __align__(16) float Xs[WD*EB];   // [n][e]
    __shared__ float Zs[EB][WD+1];              // [f][n] padded
    __shared__ float Ss[EB][EB+1];
    __shared__ float uev[EB], wfv[EB], abar[EB];
    int bt = blockIdx.x;
    int b = bt / T, t = bt % T;
    int tid = threadIdx.x;
    for (int idx = tid; idx < WD*EB; idx += 256) {
        int n = idx >> 4, e = idx & 15;
        Xs[idx] = X[((b*WD + n)*T + t)*EB + e];
    }
    __syncthreads();
    if (tid < 16) {
        float a = 0.f;
        for (int n = 0; n < WD; n++) a += Xs[n*16 + tid]*u[n];
        uev[tid] = a;
    } else if (tid < 32) {
        int f = tid - 16;
        float a = 0.f;
        for (int n = 0; n < WD; n++) a += Xs[n*16 + f]*w[n];
        wfv[f] = a;
    }
    // Z[f][n] = sum_m M[n][m] * Xs[m][f]; thread: fixed n, 8 f's
    {
        int n  = tid & 127;
        int fg = (tid >> 7)*8;
        float acc[8];
        #pragma unroll
        for (int j = 0; j < 8; j++) acc[j] = 0.f;
        for (int m = 0; m < WD; m++) {
            float mt = Mt[m*WD + n];
            const float4* xv = (const float4*)(Xs + m*16 + fg);
            float4 x0 = xv[0], x1 = xv[1];
            acc[0] += mt*x0.x; acc[1] += mt*x0.y; acc[2] += mt*x0.z; acc[3] += mt*x0.w;
            acc[4] += mt*x1.x; acc[5] += mt*x1.y; acc[6] += mt*x1.z; acc[7] += mt*x1.w;
        }
        #pragma unroll
        for (int j = 0; j < 8; j++) Zs[fg + j][n] = acc[j];
    }
    __syncthreads();
    {
        int e = tid >> 4, f = tid & 15;
        float acc = 0.f;
        for (int n = 0; n < WD; n++)
            acc += Xs[n*16 + e]*Zs[f][n];
        const float scale = 0.022097086912079608f; // 1/sqrt(2048)
        Ss[e][f] = (acc + uev[e] + wfv[f] + cptr[0])*scale;
    }
    __syncthreads();
    if (tid < 16) {
        int e = tid;
        float mx = -1e30f;
        #pragma unroll
        for (int f = 0; f < 16; f++) mx = fmaxf(mx, Ss[e][f]);
        float ex[16]; float sum = 0.f;
        #pragma unroll
        for (int f = 0; f < 16; f++) { ex[f] = expf(Ss[e][f] - mx); sum += ex[f]; }
        float inv = 1.f/sum;
        #pragma unroll
        for (int f = 0; f < 16; f++) Ss[e][f] = ex[f]*inv;
    }
    __syncthreads();
    if (tid < 16) {
        int f = tid;
        float a = 0.f;
        #pragma unroll
        for (int e = 0; e < 16; e++) a += Ss[e][f];
        abar[f] = a*(1.f/16.f);
    }
    __syncthreads();
    if (tid < 128) {
        int n = tid;
        float a = 0.f;
        #pragma unroll
        for (int f = 0; f < 16; f++) a += Xs[n*16 + f]*abar[f];
        yout[bt*WD + n] = a;
    }
}

// ---------------- attention out: Y = X + y @ Wv + bv ----------------
template<int T>
__global__ void k_attn_out(const float* __restrict__ Xin, const float* __restrict__ yv,
                           const float* __restrict__ Wv, const float* __restrict__ bv,
                           float* __restrict__ Yout) {
    __shared__ float ys[64][WD];
    const int BT = BB*T;
    int bt0 = blockIdx.y*64;
    int l = blockIdx.x*128 + (threadIdx.x & 127);
    int half = threadIdx.x >> 7;
    for (int idx = threadIdx.x; idx < 64*WD; idx += 256) {
        int r = idx >> 7, m = idx & 127;
        int bt = bt0 + r;
        ys[r][m] = (bt < BT) ? yv[bt*WD + m] : 0.f;
    }
    __syncthreads();
    float acc[32];
    #pragma unroll
    for (int j = 0; j < 32; j++) acc[j] = 0.f;
    for (int m = 0; m < WD; m++) {
        float wvv = Wv[m*LL + l];
        #pragma unroll
        for (int j = 0; j < 32; j++) acc[j] += ys[half*32 + j][m]*wvv;
    }
    float bvl = bv[l];
    int n = l >> 4, e = l & 15;
    #pragma unroll
    for (int j = 0; j < 32; j++) {
        int bt = bt0 + half*32 + j;
        if (bt < BT) {
            int b = bt / T, t = bt % T;
            int idx = ((b*WD + n)*T + t)*EB + e;
            Yout[idx] = Xin[idx] + acc[j] + bvl;
        }
    }
}

// ---------------- decode + time-mix output ----------------
__global__ void k_decode(const float* __restrict__ X, const float* __restrict__ dec_w,
                         const float* __restrict__ dec_b, const float* __restrict__ out_w,
                         const float* __restrict__ out_b, float* __restrict__ out) {
    __shared__ float sy[TF];
    int b = blockIdx.x >> 7, n = blockIdx.x & 127;
    int t = threadIdx.x;
    if (t < TF) {
        const float* xp = X + ((size_t)(b*WD + n)*TF + t)*EB;
        float a = dec_b[n];
        #pragma unroll
        for (int e = 0; e < EB; e++) a += xp[e]*dec_w[n*EB + e];
        sy[t] = a;
    }
    __syncthreads();
    if (t < ODIM) {
        float a = out_b[t];
        for (int tt = 0; tt < TF; tt++) a += sy[tt]*out_w[tt*ODIM + t];
        out[(b*ODIM + t)*WD + n] = a;
    }
}

// ---------------- launcher ----------------
extern "C" void kernel_launch(void* const* d_in, const int* in_sizes, int n_in,
                              void* d_out, int out_size) {
    const float* x_in  = (const float*)d_in[0];
    const float* emb_w = (const float*)d_in[1];
    const float* emb_b = (const float*)d_in[2];
    const float* g0_wf = (const float*)d_in[3];
    const float* g0_bf = (const float*)d_in[4];
    const float* g0_wg = (const float*)d_in[5];
    const float* g0_bg = (const float*)d_in[6];
    const float* g0_ws = (const float*)d_in[7];
    const float* g0_bs = (const float*)d_in[8];
    const float* a0_wq = (const float*)d_in[9];
    const float* a0_bq = (const float*)d_in[10];
    const float* a0_wk = (const float*)d_in[11];
    const float* a0_bk = (const float*)d_in[12];
    const float* a0_wv = (const float*)d_in[13];
    const float* a0_bv = (const float*)d_in[14];
    const float* g1_wf = (const float*)d_in[15];
    const float* g1_bf = (const float*)d_in[16];
    const float* g1_wg = (const float*)d_in[17];
    const float* g1_bg = (const float*)d_in[18];
    const float* g1_ws = (const float*)d_in[19];
    const float* g1_bs = (const float*)d_in[20];
    const float* a1_wq = (const float*)d_in[21];
    const float* a1_bq = (const float*)d_in[22];
    const float* a1_wk = (const float*)d_in[23];
    const float* a1_bk = (const float*)d_in[24];
    const float* a1_wv = (const float*)d_in[25];
    const float* a1_bv = (const float*)d_in[26];
    const float* dec_w = (const float*)d_in[27];
    const float* dec_b = (const float*)d_in[28];
    const float* out_w = (const float*)d_in[29];
    const float* out_b = (const float*)d_in[30];

    float *dA, *dB, *dMt, *dU, *dW, *dC, *dY;
    cudaGetSymbolAddress((void**)&dA,  g_bufA);
    cudaGetSymbolAddress((void**)&dB,  g_bufB);
    cudaGetSymbolAddress((void**)&dMt, g_Mt);
    cudaGetSymbolAddress((void**)&dU,  g_uu);
    cudaGetSymbolAddress((void**)&dW,  g_ww);
    cudaGetSymbolAddress((void**)&dC,  g_cc);
    cudaGetSymbolAddress((void**)&dY,  g_yv);

    // attention precompute
    k_mt<<<64, 256>>>(a0_wq, a0_wk, dMt);
    k_mt<<<64, 256>>>(a1_wq, a1_wk, dMt + WD*WD);
    k_uw<<<128, 256>>>(a0_wq, a0_wk, a0_bq, a0_bk, dU, dW, dC);
    k_uw<<<128, 256>>>(a1_wq, a1_wk, a1_bq, a1_bk, dU + WD, dW + WD, dC + 1);

    // embed
    k_embed<<<(BB*TT0*WD + 255)/256, 256>>>(x_in, emb_w, emb_b, dA);

    // layer 0: gated (TIN=128 -> 126, d=2), attention T=126
    {
        const int ntile = (126 + 3)/4;  // 32, WIDTH=6 -> 48KB smem (fits default)
        k_gated_fg<128,126,2,4><<<BB*ntile, 1024, 128*6*16*4>>>(dA, g0_wf, g0_bf, g0_wg, g0_bg, dB);
        k_gated_res<128,126><<<BB*WD, 256>>>(dA, g0_ws, g0_bs, dB);
        k_attn_scores<126><<<BB*126, 256>>>(dB, dMt, dU, dW, dC, dY);
        k_attn_out<126><<<dim3(16, (BB*126 + 63)/64), 256>>>(dB, dY, a0_wv, a0_bv, dA);
    }

    // layer 1: gated (TIN=126 -> 122, d=4), attention T=122
    {
        const int ntile = (122 + 1)/2;  // 61, WIDTH=6 -> 48KB smem (fits default)
        k_gated_fg<126,122,4,2><<<BB*ntile, 1024, 128*6*16*4>>>(dA, g1_wf, g1_bf, g1_wg, g1_bg, dB);
        k_gated_res<126,122><<<BB*WD, 256>>>(dA, g1_ws, g1_bs, dB);
        k_attn_scores<122><<<BB*122, 256>>>(dB, dMt + WD*WD, dU + WD, dW + WD, dC + 1, dY);
        k_attn_out<122><<<dim3(16, (BB*122 + 63)/64), 256>>>(dB, dY, a1_wv, a1_bv, dA);
    }

    // decode
    k_decode<<<BB*WD, 128>>>(dA, dec_w, dec_b, out_w, out_b, (float*)d_out);
}

// round 4
// speedup vs baseline: 1.2071x; 1.2071x over previous
#include <cuda_runtime.h>
#include <math.h>

#define BB   4
#define TT0  128
#define WD   128
#define EB   16
#define LL   2048
#define ODIM 24
#define TF   122

// ---------------- scratch (no allocations allowed) ----------------
__device__ float g_bufA[BB*WD*TT0*EB];   // 4 MB
__device__ float g_bufB[BB*WD*TT0*EB];   // 4 MB
__device__ float g_Mt[2*WD*WD];          // Mt[m*128+n] = (Wq Wk^T)[n][m]
__device__ float g_uu[2*WD];             // u = Wq bk
__device__ float g_ww[2*WD];             // w = Wk bq
__device__ float g_cc[2];                // c = bq . bk
__device__ float g_yv[BB*126*WD];        // per-(b,t) y vectors

// ---------------- f32x2 packed helpers ----------------
__device__ __forceinline__ unsigned long long fma2(unsigned long long a,
                                                   unsigned long long b,
                                                   unsigned long long c) {
    unsigned long long d;
    asm("fma.rn.f32x2 %0, %1, %2, %3;" : "=l"(d) : "l"(a), "l"(b), "l"(c));
    return d;
}
__device__ __forceinline__ unsigned long long pack2(float v) {
    unsigned long long r;
    asm("mov.b64 %0, {%1, %1};" : "=l"(r) : "f"(v));
    return r;
}
__device__ __forceinline__ void unpack2(unsigned long long v, float& lo, float& hi) {
    asm("mov.b64 {%0, %1}, %2;" : "=f"(lo), "=f"(hi) : "l"(v));
}

// ---------------- embed: x_in -> (B,N,T,E) ----------------
__global__ void k_embed(const float* __restrict__ x_in,
                        const float* __restrict__ emb_w,
                        const float* __restrict__ emb_b,
                        float* __restrict__ out) {
    int idx = blockIdx.x*blockDim.x + threadIdx.x;   // over B*T*N
    if (idx >= BB*TT0*WD) return;
    int n = idx & 127;
    int t = (idx >> 7) & 127;
    int b = idx >> 14;
    const float* xi = x_in + (b*TT0 + t)*131;
    float v  = xi[n];
    float f0 = xi[128], f1 = xi[129], f2 = xi[130];
    float* o = out + ((b*WD + n)*TT0 + t)*EB;
    #pragma unroll
    for (int e = 0; e < EB; e++)
        o[e] = v*emb_w[e] + f0*emb_w[16+e] + f1*emb_w[32+e] + f2*emb_w[48+e] + emb_b[e];
}

// ---------------- precompute Mt[m*128+n] = sum_l Wq[n,l]*Wk[m,l], both layers ----------------
__global__ void k_mt(const float* __restrict__ Wq0, const float* __restrict__ Wk0,
                     const float* __restrict__ Wq1, const float* __restrict__ Wk1,
                     float* __restrict__ Mt) {
    __shared__ float Aq[16][65], Ak[16][65];
    int ly = blockIdx.y;
    const float* Wq = ly ? Wq1 : Wq0;
    const float* Wk = ly ? Wk1 : Wk0;
    float* Mto = Mt + ly*WD*WD;
    int bm = blockIdx.x >> 3, bn = blockIdx.x & 7;
    int m0 = bm*16, n0 = bn*16;
    int ty = threadIdx.x >> 4, tx = threadIdx.x & 15;  // ty -> m, tx -> n
    float acc = 0.f;
    for (int l0 = 0; l0 < LL; l0 += 64) {
        #pragma unroll
        for (int r = 0; r < 4; r++) {
            int idx = threadIdx.x + r*256;
            int row = idx >> 6, col = idx & 63;
            Aq[row][col] = Wq[(n0+row)*LL + l0 + col];
            Ak[row][col] = Wk[(m0+row)*LL + l0 + col];
        }
        __syncthreads();
        #pragma unroll
        for (int lc = 0; lc < 64; lc++)
            acc += Ak[ty][lc]*Aq[tx][lc];
        __syncthreads();
    }
    Mto[(m0+ty)*WD + (n0+tx)] = acc;
}

// ---------------- precompute u, w, c (both layers) ----------------
__global__ void k_uw(const float* __restrict__ Wq0, const float* __restrict__ Wk0,
                     const float* __restrict__ bq0, const float* __restrict__ bk0,
                     const float* __restrict__ Wq1, const float* __restrict__ Wk1,
                     const float* __restrict__ bq1, const float* __restrict__ bk1,
                     float* __restrict__ u, float* __restrict__ w, float* __restrict__ cp) {
    int ly = blockIdx.y;
    const float* Wq = ly ? Wq1 : Wq0;
    const float* Wk = ly ? Wk1 : Wk0;
    const float* bq = ly ? bq1 : bq0;
    const float* bk = ly ? bk1 : bk0;
    int n = blockIdx.x;
    __shared__ float su[256], sw[256], sc[256];
    float pu = 0.f, pw = 0.f, pc = 0.f;
    for (int l = threadIdx.x; l < LL; l += 256) {
        float bkl = bk[l], bql = bq[l];
        pu += Wq[n*LL + l]*bkl;
        pw += Wk[n*LL + l]*bql;
        if (n == 0) pc += bql*bkl;
    }
    su[threadIdx.x] = pu; sw[threadIdx.x] = pw; sc[threadIdx.x] = pc;
    __syncthreads();
    for (int s = 128; s > 0; s >>= 1) {
        if (threadIdx.x < s) {
            su[threadIdx.x] += su[threadIdx.x + s];
            sw[threadIdx.x] += sw[threadIdx.x + s];
            sc[threadIdx.x] += sc[threadIdx.x + s];
        }
        __syncthreads();
    }
    if (threadIdx.x == 0) {
        u[ly*WD + n] = su[0]; w[ly*WD + n] = sw[0];
        if (n == 0) cp[ly] = sc[0];
    }
}

// ---------------- gated conv v2: smem-staged weights + f32x2 ----------------
// f[b,o,t,e] = sum_i wf[o,i,0]*X[b,i,t,e] + wf[o,i,1]*X[b,i,t+D,e] + bf[o]
// Y = tanh(f)*sigmoid(g). Thread = (o, e-quad). 512 threads. TT=4 time-tile.
template<int TIN, int TOUT, int D>
__global__ void k_gated2(const float* __restrict__ X,
                         const float* __restrict__ wf, const float* __restrict__ bf,
                         const float* __restrict__ wg, const float* __restrict__ bg,
                         float* __restrict__ Y) {
    constexpr int TT = 4;
    constexpr int WIDTH = TT + D;
    constexpr int C = 16;          // i-chunk
    constexpr int WROW = 129;      // padded row for [ict][o]
    extern __shared__ float sm[];
    float* Xs  = sm;                          // [128][WIDTH][16]
    float* Wfs = sm + WD*WIDTH*EB;            // [2*C][WROW]
    float* Wgs = Wfs + 2*C*WROW;              // [2*C][WROW]

    const int ntile = (TOUT + TT - 1)/TT;
    int b  = blockIdx.x / ntile;
    int t0 = (blockIdx.x % ntile)*TT;
    int tid = threadIdx.x;                    // 512
    int o  = tid >> 2;
    int eq = tid & 3;

    // cooperative X tile load: [i][w][e], float4 granularity
    for (int idx = tid; idx < WD*WIDTH*4; idx += 512) {
        int i = idx / (WIDTH*4);
        int r = idx - i*(WIDTH*4);
        int w = r >> 2, q = r & 3;
        int t = t0 + w;
        float4 v = make_float4(0.f, 0.f, 0.f, 0.f);
        if (t < TIN) v = *(const float4*)(X + ((b*WD + i)*TIN + t)*16 + q*4);
        *(float4*)(Xs + (i*WIDTH + w)*16 + q*4) = v;
    }

    unsigned long long fa[TT][2], ga[TT][2];
    #pragma unroll
    for (int t = 0; t < TT; t++) { fa[t][0]=0ull; fa[t][1]=0ull; ga[t][0]=0ull; ga[t][1]=0ull; }

    for (int i0 = 0; i0 < WD; i0 += C) {
        __syncthreads();   // also covers initial X load; protects Wfs reuse
        // stage weights chunk: Wfs[ict][o2] = wf[o2][i0 + ict/2][ict&1]
        for (int idx = tid; idx < WD*2*C; idx += 512) {
            int o2 = idx >> 5, ict = idx & 31;
            Wfs[ict*WROW + o2] = wf[o2*(WD*2) + i0*2 + ict];
            Wgs[ict*WROW + o2] = wg[o2*(WD*2) + i0*2 + ict];
        }
        __syncthreads();
        #pragma unroll
        for (int ic = 0; ic < C; ic++) {
            int i = i0 + ic;
            unsigned long long pf0 = pack2(Wfs[(ic*2+0)*WROW + o]);
            unsigned long long pf1 = pack2(Wfs[(ic*2+1)*WROW + o]);
            unsigned long long pg0 = pack2(Wgs[(ic*2+0)*WROW + o]);
            unsigned long long pg1 = pack2(Wgs[(ic*2+1)*WROW + o]);
            // x[w] = 4 floats at Xs[(i*WIDTH + w)*16 + eq*4]  (stride per w = 16 floats)
            unsigned long long x[WIDTH][2];
            #pragma unroll
            for (int w = 0; w < WIDTH; w++) {
                ulonglong2 v = *(const ulonglong2*)(Xs + (i*WIDTH + w)*16 + eq*4);
                x[w][0] = v.x; x[w][1] = v.y;
            }
            #pragma unroll
            for (int t = 0; t < TT; t++) {
                fa[t][0] = fma2(pf0, x[t][0],   fa[t][0]);
                fa[t][1] = fma2(pf0, x[t][1],   fa[t][1]);
                fa[t][0] = fma2(pf1, x[t+D][0], fa[t][0]);
                fa[t][1] = fma2(pf1, x[t+D][1], fa[t][1]);
                ga[t][0] = fma2(pg0, x[t][0],   ga[t][0]);
                ga[t][1] = fma2(pg0, x[t][1],   ga[t][1]);
                ga[t][0] = fma2(pg1, x[t+D][0], ga[t][0]);
                ga[t][1] = fma2(pg1, x[t+D][1], ga[t][1]);
            }
        }
    }

    float bfo = bf[o], bgo = bg[o];
    #pragma unroll
    for (int t = 0; t < TT; t++) {
        int tt = t0 + t;
        if (tt < TOUT) {
            float f0,f1,f2,f3, g0,g1,g2,g3;
            unpack2(fa[t][0], f0, f1); unpack2(fa[t][1], f2, f3);
            unpack2(ga[t][0], g0, g1); unpack2(ga[t][1], g2, g3);
            float4 r;
            r.x = tanhf(f0 + bfo)*(1.f/(1.f + expf(-(g0 + bgo))));
            r.y = tanhf(f1 + bfo)*(1.f/(1.f + expf(-(g1 + bgo))));
            r.z = tanhf(f2 + bfo)*(1.f/(1.f + expf(-(g2 + bgo))));
            r.w = tanhf(f3 + bfo)*(1.f/(1.f + expf(-(g3 + bgo))));
            *(float4*)(Y + ((b*WD + o)*TOUT + tt)*16 + eq*4) = r;
        }
    }
}

// ---------------- gated residual: Y += X @ ws + bs (over time) ----------------
template<int TIN, int TOUT>
__global__ void k_gated_res(const float* __restrict__ X, const float* __restrict__ ws,
                            const float* __restrict__ bs, float* __restrict__ Y) {
    __shared__ float Xs[TIN*EB];
    int b = blockIdx.x >> 7, n = blockIdx.x & 127;
    const float* xp = X + (size_t)(b*WD + n)*TIN*EB;
    for (int idx = threadIdx.x; idx < TIN*EB; idx += blockDim.x) Xs[idx] = xp[idx];
    __syncthreads();
    float* yp = Y + (size_t)(b*WD + n)*TOUT*EB;
    for (int idx = threadIdx.x; idx < TOUT*EB; idx += blockDim.x) {
        int s = idx >> 4, e = idx & 15;
        float acc = bs[s];
        for (int t = 0; t < TIN; t++)
            acc += Xs[t*16 + e]*ws[t*TOUT + s];
        yp[idx] += acc;
    }
}

// ---------------- attention scores -> y[b,t,n] ----------------
template<int T>
__global__ void k_attn_scores(const float* __restrict__ X, const float* __restrict__ Mt,
                              const float* __restrict__ u, const float* __restrict__ w,
                              const float* __restrict__ cptr, float* __restrict__ yout) {
    __shared__ __align__(16) float Xs[WD*EB];   // [n][e]
    __shared__ float Zs[EB][WD+1];              // [f][n] padded
    __shared__ float Ss[EB][EB+1];
    __shared__ float uev[EB], wfv[EB], abar[EB];
    int bt = blockIdx.x;
    int b = bt / T, t = bt % T;
    int tid = threadIdx.x;
    for (int idx = tid; idx < WD*EB; idx += 256) {
        int n = idx >> 4, e = idx & 15;
        Xs[idx] = X[((b*WD + n)*T + t)*EB + e];
    }
    __syncthreads();
    if (tid < 16) {
        float a = 0.f;
        for (int n = 0; n < WD; n++) a += Xs[n*16 + tid]*u[n];
        uev[tid] = a;
    } else if (tid < 32) {
        int f = tid - 16;
        float a = 0.f;
        for (int n = 0; n < WD; n++) a += Xs[n*16 + f]*w[n];
        wfv[f] = a;
    }
    // Z[f][n] = sum_m M[n][m] * Xs[m][f]; thread: fixed n, 8 f's
    {
        int n  = tid & 127;
        int fg = (tid >> 7)*8;
        float acc[8];
        #pragma unroll
        for (int j = 0; j < 8; j++) acc[j] = 0.f;
        for (int m = 0; m < WD; m++) {
            float mt = Mt[m*WD + n];
            const float4* xv = (const float4*)(Xs + m*16 + fg);
            float4 x0 = xv[0], x1 = xv[1];
            acc[0] += mt*x0.x; acc[1] += mt*x0.y; acc[2] += mt*x0.z; acc[3] += mt*x0.w;
            acc[4] += mt*x1.x; acc[5] += mt*x1.y; acc[6] += mt*x1.z; acc[7] += mt*x1.w;
        }
        #pragma unroll
        for (int j = 0; j < 8; j++) Zs[fg + j][n] = acc[j];
    }
    __syncthreads();
    {
        int e = tid >> 4, f = tid & 15;
        float acc = 0.f;
        for (int n = 0; n < WD; n++)
            acc += Xs[n*16 + e]*Zs[f][n];
        const float scale = 0.022097086912079608f; // 1/sqrt(2048)
        Ss[e][f] = (acc + uev[e] + wfv[f] + cptr[0])*scale;
    }
    __syncthreads();
    if (tid < 16) {
        int e = tid;
        float mx = -1e30f;
        #pragma unroll
        for (int f = 0; f < 16; f++) mx = fmaxf(mx, Ss[e][f]);
        float ex[16]; float sum = 0.f;
        #pragma unroll
        for (int f = 0; f < 16; f++) { ex[f] = expf(Ss[e][f] - mx); sum += ex[f]; }
        float inv = 1.f/sum;
        #pragma unroll
        for (int f = 0; f < 16; f++) Ss[e][f] = ex[f]*inv;
    }
    __syncthreads();
    if (tid < 16) {
        int f = tid;
        float a = 0.f;
        #pragma unroll
        for (int e = 0; e < 16; e++) a += Ss[e][f];
        abar[f] = a*(1.f/16.f);
    }
    __syncthreads();
    if (tid < 128) {
        int n = tid;
        float a = 0.f;
        #pragma unroll
        for (int f = 0; f < 16; f++) a += Xs[n*16 + f]*abar[f];
        yout[bt*WD + n] = a;
    }
}

// ---------------- attention out: Y = X + y @ Wv + bv ----------------
template<int T>
__global__ void k_attn_out(const float* __restrict__ Xin, const float* __restrict__ yv,
                           const float* __restrict__ Wv, const float* __restrict__ bv,
                           float* __restrict__ Yout) {
    __shared__ float ys[64][WD];
    const int BT = BB*T;
    int bt0 = blockIdx.y*64;
    int l = blockIdx.x*128 + (threadIdx.x & 127);
    int half = threadIdx.x >> 7;
    for (int idx = threadIdx.x; idx < 64*WD; idx += 256) {
        int r = idx >> 7, m = idx & 127;
        int bt = bt0 + r;
        ys[r][m] = (bt < BT) ? yv[bt*WD + m] : 0.f;
    }
    __syncthreads();
    float acc[32];
    #pragma unroll
    for (int j = 0; j < 32; j++) acc[j] = 0.f;
    for (int m = 0; m < WD; m++) {
        float wvv = Wv[m*LL + l];
        #pragma unroll
        for (int j = 0; j < 32; j++) acc[j] += ys[half*32 + j][m]*wvv;
    }
    float bvl = bv[l];
    int n = l >> 4, e = l & 15;
    #pragma unroll
    for (int j = 0; j < 32; j++) {
        int bt = bt0 + half*32 + j;
        if (bt < BT) {
            int b = bt / T, t = bt % T;
            int idx = ((b*WD + n)*T + t)*EB + e;
            Yout[idx] = Xin[idx] + acc[j] + bvl;
        }
    }
}

// ---------------- decode + time-mix output ----------------
__global__ void k_decode(const float* __restrict__ X, const float* __restrict__ dec_w,
                         const float* __restrict__ dec_b, const float* __restrict__ out_w,
                         const float* __restrict__ out_b, float* __restrict__ out) {
    __shared__ float sy[TF];
    int b = blockIdx.x >> 7, n = blockIdx.x & 127;
    int t = threadIdx.x;
    if (t < TF) {
        const float* xp = X + ((size_t)(b*WD + n)*TF + t)*EB;
        float a = dec_b[n];
        #pragma unroll
        for (int e = 0; e < EB; e++) a += xp[e]*dec_w[n*EB + e];
        sy[t] = a;
    }
    __syncthreads();
    if (t < ODIM) {
        float a = out_b[t];
        for (int tt = 0; tt < TF; tt++) a += sy[tt]*out_w[tt*ODIM + t];
        out[(b*ODIM + t)*WD + n] = a;
    }
}

// ---------------- launcher ----------------
extern "C" void kernel_launch(void* const* d_in, const int* in_sizes, int n_in,
                              void* d_out, int out_size) {
    const float* x_in  = (const float*)d_in[0];
    const float* emb_w = (const float*)d_in[1];
    const float* emb_b = (const float*)d_in[2];
    const float* g0_wf = (const float*)d_in[3];
    const float* g0_bf = (const float*)d_in[4];
    const float* g0_wg = (const float*)d_in[5];
    const float* g0_bg = (const float*)d_in[6];
    const float* g0_ws = (const float*)d_in[7];
    const float* g0_bs = (const float*)d_in[8];
    const float* a0_wq = (const float*)d_in[9];
    const float* a0_bq = (const float*)d_in[10];
    const float* a0_wk = (const float*)d_in[11];
    const float* a0_bk = (const float*)d_in[12];
    const float* a0_wv = (const float*)d_in[13];
    const float* a0_bv = (const float*)d_in[14];
    const float* g1_wf = (const float*)d_in[15];
    const float* g1_bf = (const float*)d_in[16];
    const float* g1_wg = (const float*)d_in[17];
    const float* g1_bg = (const float*)d_in[18];
    const float* g1_ws = (const float*)d_in[19];
    const float* g1_bs = (const float*)d_in[20];
    const float* a1_wq = (const float*)d_in[21];
    const float* a1_bq = (const float*)d_in[22];
    const float* a1_wk = (const float*)d_in[23];
    const float* a1_bk = (const float*)d_in[24];
    const float* a1_wv = (const float*)d_in[25];
    const float* a1_bv = (const float*)d_in[26];
    const float* dec_w = (const float*)d_in[27];
    const float* dec_b = (const float*)d_in[28];
    const float* out_w = (const float*)d_in[29];
    const float* out_b = (const float*)d_in[30];

    float *dA, *dB, *dMt, *dU, *dW, *dC, *dY;
    cudaGetSymbolAddress((void**)&dA,  g_bufA);
    cudaGetSymbolAddress((void**)&dB,  g_bufB);
    cudaGetSymbolAddress((void**)&dMt, g_Mt);
    cudaGetSymbolAddress((void**)&dU,  g_uu);
    cudaGetSymbolAddress((void**)&dW,  g_ww);
    cudaGetSymbolAddress((void**)&dC,  g_cc);
    cudaGetSymbolAddress((void**)&dY,  g_yv);

    // opt-in to >48KB dynamic smem for gated kernels (idempotent, host-side)
    const int SMEM_G0 = (WD*6*EB + 2*2*16*129)*4;   // 49152 + 33024 = 82176
    const int SMEM_G1 = (WD*8*EB + 2*2*16*129)*4;   // 65536 + 33024 = 98560
    cudaFuncSetAttribute(k_gated2<128,126,2>, cudaFuncAttributeMaxDynamicSharedMemorySize, SMEM_G0);
    cudaFuncSetAttribute(k_gated2<126,122,4>, cudaFuncAttributeMaxDynamicSharedMemorySize, SMEM_G1);

    // embed + attention precompute (merged launches)
    k_embed<<<(BB*TT0*WD + 255)/256, 256>>>(x_in, emb_w, emb_b, dA);
    k_mt<<<dim3(64,2), 256>>>(a0_wq, a0_wk, a1_wq, a1_wk, dMt);
    k_uw<<<dim3(128,2), 256>>>(a0_wq, a0_wk, a0_bq, a0_bk,
                               a1_wq, a1_wk, a1_bq, a1_bk, dU, dW, dC);

    // layer 0: gated (TIN=128 -> 126, d=2), attention T=126
    {
        const int ntile = (126 + 3)/4;  // 32
        k_gated2<128,126,2><<<BB*ntile, 512, SMEM_G0>>>(dA, g0_wf, g0_bf, g0_wg, g0_bg, dB);
        k_gated_res<128,126><<<BB*WD, 256>>>(dA, g0_ws, g0_bs, dB);
        k_attn_scores<126><<<BB*126, 256>>>(dB, dMt, dU, dW, dC, dY);
        k_attn_out<126><<<dim3(16, (BB*126 + 63)/64), 256>>>(dB, dY, a0_wv, a0_bv, dA);
    }

    // layer 1: gated (TIN=126 -> 122, d=4), attention T=122
    {
        const int ntile = (122 + 3)/4;  // 31
        k_gated2<126,122,4><<<BB*ntile, 512, SMEM_G1>>>(dA, g1_wf, g1_bf, g1_wg, g1_bg, dB);
        k_gated_res<126,122><<<BB*WD, 256>>>(dA, g1_ws, g1_bs, dB);
        k_attn_scores<122><<<BB*122, 256>>>(dB, dMt + WD*WD, dU + WD, dW + WD, dC + 1, dY);
        k_attn_out<122><<<dim3(16, (BB*122 + 63)/64), 256>>>(dB, dY, a1_wv, a1_bv, dA);
    }

    // decode
    k_decode<<<BB*WD, 128>>>(dA, dec_w, dec_b, out_w, out_b, (float*)d_out);
}

// round 5
// speedup vs baseline: 1.2623x; 1.0458x over previous
#include <cuda_runtime.h>
#include <math.h>

#define BB   4
#define TT0  128
#define WD   128
#define EB   16
#define LL   2048
#define ODIM 24
#define TF   122

// ---------------- scratch (no allocations allowed) ----------------
__device__ float g_bufA[BB*WD*TT0*EB];   // 4 MB
__device__ float g_bufB[BB*WD*TT0*EB];   // 4 MB
__device__ float g_Mt[2*WD*WD];          // Mt[m*128+n] = (Wq Wk^T)[n][m]
__device__ float g_uu[2*WD];             // u = Wq bk
__device__ float g_ww[2*WD];             // w = Wk bq
__device__ float g_cc[2];                // c = bq . bk
__device__ float g_yv[BB*126*WD];        // per-(b,t) y vectors

// ---------------- f32x2 packed helpers ----------------
__device__ __forceinline__ unsigned long long fma2(unsigned long long a,
                                                   unsigned long long b,
                                                   unsigned long long c) {
    unsigned long long d;
    asm("fma.rn.f32x2 %0, %1, %2, %3;" : "=l"(d) : "l"(a), "l"(b), "l"(c));
    return d;
}
__device__ __forceinline__ unsigned long long pack2(float v) {
    unsigned long long r;
    asm("mov.b64 %0, {%1, %1};" : "=l"(r) : "f"(v));
    return r;
}
__device__ __forceinline__ void unpack2(unsigned long long v, float& lo, float& hi) {
    asm("mov.b64 {%0, %1}, %2;" : "=f"(lo), "=f"(hi) : "l"(v));
}

// ---------------- embed: x_in -> (B,N,T,E) ----------------
__global__ void k_embed(const float* __restrict__ x_in,
                        const float* __restrict__ emb_w,
                        const float* __restrict__ emb_b,
                        float* __restrict__ out) {
    int idx = blockIdx.x*blockDim.x + threadIdx.x;   // over B*T*N
    if (idx >= BB*TT0*WD) return;
    int n = idx & 127;
    int t = (idx >> 7) & 127;
    int b = idx >> 14;
    const float* xi = x_in + (b*TT0 + t)*131;
    float v  = xi[n];
    float f0 = xi[128], f1 = xi[129], f2 = xi[130];
    float* o = out + ((b*WD + n)*TT0 + t)*EB;
    #pragma unroll
    for (int e = 0; e < EB; e++)
        o[e] = v*emb_w[e] + f0*emb_w[16+e] + f1*emb_w[32+e] + f2*emb_w[48+e] + emb_b[e];
}

// ---------------- precompute Mt[m*128+n] = sum_l Wq[n,l]*Wk[m,l], both layers ----------------
__global__ void k_mt(const float* __restrict__ Wq0, const float* __restrict__ Wk0,
                     const float* __restrict__ Wq1, const float* __restrict__ Wk1,
                     float* __restrict__ Mt) {
    __shared__ float Aq[16][65], Ak[16][65];
    int ly = blockIdx.y;
    const float* Wq = ly ? Wq1 : Wq0;
    const float* Wk = ly ? Wk1 : Wk0;
    float* Mto = Mt + ly*WD*WD;
    int bm = blockIdx.x >> 3, bn = blockIdx.x & 7;
    int m0 = bm*16, n0 = bn*16;
    int ty = threadIdx.x >> 4, tx = threadIdx.x & 15;  // ty -> m, tx -> n
    float acc = 0.f;
    for (int l0 = 0; l0 < LL; l0 += 64) {
        #pragma unroll
        for (int r = 0; r < 4; r++) {
            int idx = threadIdx.x + r*256;
            int row = idx >> 6, col = idx & 63;
            Aq[row][col] = Wq[(n0+row)*LL + l0 + col];
            Ak[row][col] = Wk[(m0+row)*LL + l0 + col];
        }
        __syncthreads();
        #pragma unroll
        for (int lc = 0; lc < 64; lc++)
            acc += Ak[ty][lc]*Aq[tx][lc];
        __syncthreads();
    }
    Mto[(m0+ty)*WD + (n0+tx)] = acc;
}

// ---------------- precompute u, w, c (both layers) ----------------
__global__ void k_uw(const float* __restrict__ Wq0, const float* __restrict__ Wk0,
                     const float* __restrict__ bq0, const float* __restrict__ bk0,
                     const float* __restrict__ Wq1, const float* __restrict__ Wk1,
                     const float* __restrict__ bq1, const float* __restrict__ bk1,
                     float* __restrict__ u, float* __restrict__ w, float* __restrict__ cp) {
    int ly = blockIdx.y;
    const float* Wq = ly ? Wq1 : Wq0;
    const float* Wk = ly ? Wk1 : Wk0;
    const float* bq = ly ? bq1 : bq0;
    const float* bk = ly ? bk1 : bk0;
    int n = blockIdx.x;
    __shared__ float su[256], sw[256], sc[256];
    float pu = 0.f, pw = 0.f, pc = 0.f;
    for (int l = threadIdx.x; l < LL; l += 256) {
        float bkl = bk[l], bql = bq[l];
        pu += Wq[n*LL + l]*bkl;
        pw += Wk[n*LL + l]*bql;
        if (n == 0) pc += bql*bkl;
    }
    su[threadIdx.x] = pu; sw[threadIdx.x] = pw; sc[threadIdx.x] = pc;
    __syncthreads();
    for (int s = 128; s > 0; s >>= 1) {
        if (threadIdx.x < s) {
            su[threadIdx.x] += su[threadIdx.x + s];
            sw[threadIdx.x] += sw[threadIdx.x + s];
            sc[threadIdx.x] += sc[threadIdx.x + s];
        }
        __syncthreads();
    }
    if (threadIdx.x == 0) {
        u[ly*WD + n] = su[0]; w[ly*WD + n] = sw[0];
        if (n == 0) cp[ly] = sc[0];
    }
}

// ---------------- gated conv v3: o-split, smem weights, f32x2 ----------------
// f[b,o,t,e] = sum_i wf[o,i,0]*X[b,i,t,e] + wf[o,i,1]*X[b,i,t+D,e] + bf[o]
// Y = tanh(f)*sigmoid(g). Block: 256 threads = 64 o x 4 eq; grid = B*ntile*2.
template<int TIN, int TOUT, int D>
__global__ void k_gated3(const float* __restrict__ X,
                         const float* __restrict__ wf, const float* __restrict__ bf,
                         const float* __restrict__ wg, const float* __restrict__ bg,
                         float* __restrict__ Y) {
    constexpr int TT = 4;
    constexpr int WIDTH = TT + D;
    constexpr int C = 16;          // i-chunk
    constexpr int WROW = 65;       // padded row for [ict][o_local]
    extern __shared__ float sm[];
    float* Xs  = sm;                          // [128][WIDTH][16]
    float* Wfs = sm + WD*WIDTH*EB;            // [2*C][WROW]
    float* Wgs = Wfs + 2*C*WROW;              // [2*C][WROW]

    const int ntile = (TOUT + TT - 1)/TT;
    int bid = blockIdx.x;
    int bo  = bid & 1;                        // o-half
    int bt  = bid >> 1;
    int b   = bt / ntile;
    int t0  = (bt % ntile)*TT;
    int tid = threadIdx.x;                    // 256
    int ol  = tid >> 2;                       // 0..63
    int o   = bo*64 + ol;
    int eq  = tid & 3;

    // cooperative X tile load: [i][w][e], float4 granularity
    for (int idx = tid; idx < WD*WIDTH*4; idx += 256) {
        int i = idx / (WIDTH*4);
        int r = idx - i*(WIDTH*4);
        int w = r >> 2, q = r & 3;
        int t = t0 + w;
        float4 v = make_float4(0.f, 0.f, 0.f, 0.f);
        if (t < TIN) v = *(const float4*)(X + ((b*WD + i)*TIN + t)*16 + q*4);
        *(float4*)(Xs + (i*WIDTH + w)*16 + q*4) = v;
    }

    unsigned long long fa[TT][2], ga[TT][2];
    #pragma unroll
    for (int t = 0; t < TT; t++) { fa[t][0]=0ull; fa[t][1]=0ull; ga[t][0]=0ull; ga[t][1]=0ull; }

    for (int i0 = 0; i0 < WD; i0 += C) {
        __syncthreads();   // also covers initial X load; protects Wfs reuse
        // stage weights chunk for this o-half: Wfs[ict][o2] = wf[bo*64+o2][i0 + ict/2][ict&1]
        for (int idx = tid; idx < 64*2*C; idx += 256) {
            int o2 = idx >> 5, ict = idx & 31;
            Wfs[ict*WROW + o2] = wf[(bo*64 + o2)*(WD*2) + i0*2 + ict];
            Wgs[ict*WROW + o2] = wg[(bo*64 + o2)*(WD*2) + i0*2 + ict];
        }
        __syncthreads();
        #pragma unroll
        for (int ic = 0; ic < C; ic++) {
            int i = i0 + ic;
            unsigned long long pf0 = pack2(Wfs[(ic*2+0)*WROW + ol]);
            unsigned long long pf1 = pack2(Wfs[(ic*2+1)*WROW + ol]);
            unsigned long long pg0 = pack2(Wgs[(ic*2+0)*WROW + ol]);
            unsigned long long pg1 = pack2(Wgs[(ic*2+1)*WROW + ol]);
            unsigned long long x[WIDTH][2];
            #pragma unroll
            for (int w = 0; w < WIDTH; w++) {
                ulonglong2 v = *(const ulonglong2*)(Xs + (i*WIDTH + w)*16 + eq*4);
                x[w][0] = v.x; x[w][1] = v.y;
            }
            #pragma unroll
            for (int t = 0; t < TT; t++) {
                fa[t][0] = fma2(pf0, x[t][0],   fa[t][0]);
                fa[t][1] = fma2(pf0, x[t][1],   fa[t][1]);
                fa[t][0] = fma2(pf1, x[t+D][0], fa[t][0]);
                fa[t][1] = fma2(pf1, x[t+D][1], fa[t][1]);
                ga[t][0] = fma2(pg0, x[t][0],   ga[t][0]);
                ga[t][1] = fma2(pg0, x[t][1],   ga[t][1]);
                ga[t][0] = fma2(pg1, x[t+D][0], ga[t][0]);
                ga[t][1] = fma2(pg1, x[t+D][1], ga[t][1]);
            }
        }
    }

    float bfo = bf[o], bgo = bg[o];
    #pragma unroll
    for (int t = 0; t < TT; t++) {
        int tt = t0 + t;
        if (tt < TOUT) {
            float f0,f1,f2,f3, g0,g1,g2,g3;
            unpack2(fa[t][0], f0, f1); unpack2(fa[t][1], f2, f3);
            unpack2(ga[t][0], g0, g1); unpack2(ga[t][1], g2, g3);
            float4 r;
            r.x = tanhf(f0 + bfo)*(1.f/(1.f + expf(-(g0 + bgo))));
            r.y = tanhf(f1 + bfo)*(1.f/(1.f + expf(-(g1 + bgo))));
            r.z = tanhf(f2 + bfo)*(1.f/(1.f + expf(-(g2 + bgo))));
            r.w = tanhf(f3 + bfo)*(1.f/(1.f + expf(-(g3 + bgo))));
            *(float4*)(Y + ((b*WD + o)*TOUT + tt)*16 + eq*4) = r;
        }
    }
}

// ---------------- gated residual v2: tiled smem GEMM ----------------
// out[b,n,s,e] += sum_t X[b,n,t,e]*ws[t,s] + bs[s]
// rows = (n,e): 2048 per b; 64 rows/block -> grid = BB*32 = 128 blocks, 256 thr.
template<int TIN, int TOUT>
__global__ void k_res2(const float* __restrict__ X, const float* __restrict__ ws,
                       const float* __restrict__ bs, float* __restrict__ Y) {
    constexpr int RPB = 64;
    constexpr int KC  = 32;
    __shared__ float As[KC][RPB];       // [t][row]
    __shared__ float Ws[KC][132];       // [t][s], 16B-aligned rows
    int b  = blockIdx.x >> 5;
    int r0 = (blockIdx.x & 31)*RPB;
    int tid = threadIdx.x;              // 256
    int rq = tid >> 4;                  // 0..15 -> rows rq*4..+3
    int sg = tid & 15;                  // s = sg*8 .. +7

    unsigned long long acc[4][4];
    #pragma unroll
    for (int r = 0; r < 4; r++)
        #pragma unroll
        for (int j = 0; j < 4; j++) acc[r][j] = 0ull;

    for (int t0 = 0; t0 < TIN; t0 += KC) {
        __syncthreads();
        // A chunk: 64 rows x 32 t (8 per thread)
        #pragma unroll
        for (int j = 0; j < (RPB*KC)/256; j++) {
            int idx = tid + j*256;
            int row = idx & (RPB-1);
            int t = idx >> 6;
            int rr = r0 + row;
            int n = rr >> 4, e = rr & 15;
            int tg = t0 + t;
            As[t][row] = (tg < TIN) ? X[((b*WD + n)*TIN + tg)*EB + e] : 0.f;
        }
        // ws chunk: 32 t x 128 s padded (16 per thread)
        #pragma unroll
        for (int j = 0; j < (KC*128)/256; j++) {
            int idx = tid + j*256;
            int s = idx & 127;
            int t = idx >> 7;
            int tg = t0 + t;
            Ws[t][s] = (tg < TIN && s < TOUT) ? ws[tg*TOUT + s] : 0.f;
        }
        __syncthreads();
        #pragma unroll
        for (int t = 0; t < KC; t++) {
            float4 w0 = *(const float4*)(&Ws[t][sg*8]);
            float4 w1 = *(const float4*)(&Ws[t][sg*8 + 4]);
            unsigned long long wv[4];
            wv[0] = ((unsigned long long)__float_as_uint(w0.y) << 32) | __float_as_uint(w0.x);
            wv[1] = ((unsigned long long)__float_as_uint(w0.w) << 32) | __float_as_uint(w0.z);
            wv[2] = ((unsigned long long)__float_as_uint(w1.y) << 32) | __float_as_uint(w1.x);
            wv[3] = ((unsigned long long)__float_as_uint(w1.w) << 32) | __float_as_uint(w1.z);
            #pragma unroll
            for (int r = 0; r < 4; r++) {
                unsigned long long av = pack2(As[t][rq*4 + r]);
                #pragma unroll
                for (int j = 0; j < 4; j++)
                    acc[r][j] = fma2(av, wv[j], acc[r][j]);
            }
        }
    }
    #pragma unroll
    for (int r = 0; r < 4; r++) {
        int rr = r0 + rq*4 + r;
        int n = rr >> 4, e = rr & 15;
        float* yp = Y + ((size_t)(b*WD + n)*TOUT)*EB + e;
        #pragma unroll
        for (int j = 0; j < 4; j++) {
            float lo, hi; unpack2(acc[r][j], lo, hi);
            int s0 = sg*8 + j*2;
            if (s0 < TOUT)   yp[s0*EB]       += lo + bs[s0];
            if (s0+1 < TOUT) yp[(s0+1)*EB]   += hi + bs[s0+1];
        }
    }
}

// ---------------- attention scores -> y[b,t,n] ----------------
template<int T>
__global__ void k_attn_scores(const float* __restrict__ X, const float* __restrict__ Mt,
                              const float* __restrict__ u, const float* __restrict__ w,
                              const float* __restrict__ cptr, float* __restrict__ yout) {
    __shared__ __align__(16) float Xs[WD*EB];   // [n][e]
    __shared__ float Zs[EB][WD+1];              // [f][n] padded
    __shared__ float Ss[EB][EB+1];
    __shared__ float uev[EB], wfv[EB], abar[EB];
    int bt = blockIdx.x;
    int b = bt / T, t = bt % T;
    int tid = threadIdx.x;
    for (int idx = tid; idx < WD*EB; idx += 256) {
        int n = idx >> 4, e = idx & 15;
        Xs[idx] = X[((b*WD + n)*T + t)*EB + e];
    }
    __syncthreads();
    if (tid < 16) {
        float a = 0.f;
        for (int n = 0; n < WD; n++) a += Xs[n*16 + tid]*u[n];
        uev[tid] = a;
    } else if (tid < 32) {
        int f = tid - 16;
        float a = 0.f;
        for (int n = 0; n < WD; n++) a += Xs[n*16 + f]*w[n];
        wfv[f] = a;
    }
    // Z[f][n] = sum_m M[n][m] * Xs[m][f]; thread: fixed n, 8 f's
    {
        int n  = tid & 127;
        int fg = (tid >> 7)*8;
        float acc[8];
        #pragma unroll
        for (int j = 0; j < 8; j++) acc[j] = 0.f;
        for (int m = 0; m < WD; m++) {
            float mt = Mt[m*WD + n];
            const float4* xv = (const float4*)(Xs + m*16 + fg);
            float4 x0 = xv[0], x1 = xv[1];
            acc[0] += mt*x0.x; acc[1] += mt*x0.y; acc[2] += mt*x0.z; acc[3] += mt*x0.w;
            acc[4] += mt*x1.x; acc[5] += mt*x1.y; acc[6] += mt*x1.z; acc[7] += mt*x1.w;
        }
        #pragma unroll
        for (int j = 0; j < 8; j++) Zs[fg + j][n] = acc[j];
    }
    __syncthreads();
    {
        int e = tid >> 4, f = tid & 15;
        float acc = 0.f;
        for (int n = 0; n < WD; n++)
            acc += Xs[n*16 + e]*Zs[f][n];
        const float scale = 0.022097086912079608f; // 1/sqrt(2048)
        Ss[e][f] = (acc + uev[e] + wfv[f] + cptr[0])*scale;
    }
    __syncthreads();
    if (tid < 16) {
        int e = tid;
        float mx = -1e30f;
        #pragma unroll
        for (int f = 0; f < 16; f++) mx = fmaxf(mx, Ss[e][f]);
        float ex[16]; float sum = 0.f;
        #pragma unroll
        for (int f = 0; f < 16; f++) { ex[f] = expf(Ss[e][f] - mx); sum += ex[f]; }
        float inv = 1.f/sum;
        #pragma unroll
        for (int f = 0; f < 16; f++) Ss[e][f] = ex[f]*inv;
    }
    __syncthreads();
    if (tid < 16) {
        int f = tid;
        float a = 0.f;
        #pragma unroll
        for (int e = 0; e < 16; e++) a += Ss[e][f];
        abar[f] = a*(1.f/16.f);
    }
    __syncthreads();
    if (tid < 128) {
        int n = tid;
        float a = 0.f;
        #pragma unroll
        for (int f = 0; f < 16; f++) a += Xs[n*16 + f]*abar[f];
        yout[bt*WD + n] = a;
    }
}

// ---------------- attention out: Y = X + y @ Wv + bv ----------------
template<int T>
__global__ void k_attn_out(const float* __restrict__ Xin, const float* __restrict__ yv,
                           const float* __restrict__ Wv, const float* __restrict__ bv,
                           float* __restrict__ Yout) {
    __shared__ float ys[64][WD];
    const int BT = BB*T;
    int bt0 = blockIdx.y*64;
    int l = blockIdx.x*128 + (threadIdx.x & 127);
    int half = threadIdx.x >> 7;
    for (int idx = threadIdx.x; idx < 64*WD; idx += 256) {
        int r = idx >> 7, m = idx & 127;
        int bt = bt0 + r;
        ys[r][m] = (bt < BT) ? yv[bt*WD + m] : 0.f;
    }
    __syncthreads();
    float acc[32];
    #pragma unroll
    for (int j = 0; j < 32; j++) acc[j] = 0.f;
    for (int m = 0; m < WD; m++) {
        float wvv = Wv[m*LL + l];
        #pragma unroll
        for (int j = 0; j < 32; j++) acc[j] += ys[half*32 + j][m]*wvv;
    }
    float bvl = bv[l];
    int n = l >> 4, e = l & 15;
    #pragma unroll
    for (int j = 0; j < 32; j++) {
        int bt = bt0 + half*32 + j;
        if (bt < BT) {
            int b = bt / T, t = bt % T;
            int idx = ((b*WD + n)*T + t)*EB + e;
            Yout[idx] = Xin[idx] + acc[j] + bvl;
        }
    }
}

// ---------------- decode + time-mix output ----------------
__global__ void k_decode(const float* __restrict__ X, const float* __restrict__ dec_w,
                         const float* __restrict__ dec_b, const float* __restrict__ out_w,
                         const float* __restrict__ out_b, float* __restrict__ out) {
    __shared__ float sy[TF];
    int b = blockIdx.x >> 7, n = blockIdx.x & 127;
    int t = threadIdx.x;
    if (t < TF) {
        const float* xp = X + ((size_t)(b*WD + n)*TF + t)*EB;
        float a = dec_b[n];
        #pragma unroll
        for (int e = 0; e < EB; e++) a += xp[e]*dec_w[n*EB + e];
        sy[t] = a;
    }
    __syncthreads();
    if (t < ODIM) {
        float a = out_b[t];
        for (int tt = 0; tt < TF; tt++) a += sy[tt]*out_w[tt*ODIM + t];
        out[(b*ODIM + t)*WD + n] = a;
    }
}

// ---------------- launcher ----------------
extern "C" void kernel_launch(void* const* d_in, const int* in_sizes, int n_in,
                              void* d_out, int out_size) {
    const float* x_in  = (const float*)d_in[0];
    const float* emb_w = (const float*)d_in[1];
    const float* emb_b = (const float*)d_in[2];
    const float* g0_wf = (const float*)d_in[3];
    const float* g0_bf = (const float*)d_in[4];
    const float* g0_wg = (const float*)d_in[5];
    const float* g0_bg = (const float*)d_in[6];
    const float* g0_ws = (const float*)d_in[7];
    const float* g0_bs = (const float*)d_in[8];
    const float* a0_wq = (const float*)d_in[9];
    const float* a0_bq = (const float*)d_in[10];
    const float* a0_wk = (const float*)d_in[11];
    const float* a0_bk = (const float*)d_in[12];
    const float* a0_wv = (const float*)d_in[13];
    const float* a0_bv = (const float*)d_in[14];
    const float* g1_wf = (const float*)d_in[15];
    const float* g1_bf = (const float*)d_in[16];
    const float* g1_wg = (const float*)d_in[17];
    const float* g1_bg = (const float*)d_in[18];
    const float* g1_ws = (const float*)d_in[19];
    const float* g1_bs = (const float*)d_in[20];
    const float* a1_wq = (const float*)d_in[21];
    const float* a1_bq = (const float*)d_in[22];
    const float* a1_wk = (const float*)d_in[23];
    const float* a1_bk = (const float*)d_in[24];
    const float* a1_wv = (const float*)d_in[25];
    const float* a1_bv = (const float*)d_in[26];
    const float* dec_w = (const float*)d_in[27];
    const float* dec_b = (const float*)d_in[28];
    const float* out_w = (const float*)d_in[29];
    const float* out_b = (const float*)d_in[30];

    float *dA, *dB, *dMt, *dU, *dW, *dC, *dY;
    cudaGetSymbolAddress((void**)&dA,  g_bufA);
    cudaGetSymbolAddress((void**)&dB,  g_bufB);
    cudaGetSymbolAddress((void**)&dMt, g_Mt);
    cudaGetSymbolAddress((void**)&dU,  g_uu);
    cudaGetSymbolAddress((void**)&dW,  g_ww);
    cudaGetSymbolAddress((void**)&dC,  g_cc);
    cudaGetSymbolAddress((void**)&dY,  g_yv);

    // opt-in to >48KB dynamic smem for gated kernels (idempotent, host-side)
    const int SMEM_G0 = (WD*6*EB + 2*2*16*65)*4;    // 49152 + 16640 = 65792
    const int SMEM_G1 = (WD*8*EB + 2*2*16*65)*4;    // 65536 + 16640 = 82176
    cudaFuncSetAttribute(k_gated3<128,126,2>, cudaFuncAttributeMaxDynamicSharedMemorySize, SMEM_G0);
    cudaFuncSetAttribute(k_gated3<126,122,4>, cudaFuncAttributeMaxDynamicSharedMemorySize, SMEM_G1);

    // embed + attention precompute (merged launches)
    k_embed<<<(BB*TT0*WD + 255)/256, 256>>>(x_in, emb_w, emb_b, dA);
    k_mt<<<dim3(64,2), 256>>>(a0_wq, a0_wk, a1_wq, a1_wk, dMt);
    k_uw<<<dim3(128,2), 256>>>(a0_wq, a0_wk, a0_bq, a0_bk,
                               a1_wq, a1_wk, a1_bq, a1_bk, dU, dW, dC);

    // layer 0: gated (TIN=128 -> 126, d=2), attention T=126
    {
        const int ntile = (126 + 3)/4;  // 32
        k_gated3<128,126,2><<<BB*ntile*2, 256, SMEM_G0>>>(dA, g0_wf, g0_bf, g0_wg, g0_bg, dB);
        k_res2<128,126><<<BB*32, 256>>>(dA, g0_ws, g0_bs, dB);
        k_attn_scores<126><<<BB*126, 256>>>(dB, dMt, dU, dW, dC, dY);
        k_attn_out<126><<<dim3(16, (BB*126 + 63)/64), 256>>>(dB, dY, a0_wv, a0_bv, dA);
    }

    // layer 1: gated (TIN=126 -> 122, d=4), attention T=122
    {
        const int ntile = (122 + 3)/4;  // 31
        k_gated3<126,122,4><<<BB*ntile*2, 256, SMEM_G1>>>(dA, g1_wf, g1_bf, g1_wg, g1_bg, dB);
        k_res2<126,122><<<BB*32, 256>>>(dA, g1_ws, g1_bs, dB);
        k_attn_scores<122><<<BB*122, 256>>>(dB, dMt + WD*WD, dU + WD, dW + WD, dC + 1, dY);
        k_attn_out<122><<<dim3(16, (BB*122 + 63)/64), 256>>>(dB, dY, a1_wv, a1_bv, dA);
    }

    // decode
    k_decode<<<BB*WD, 128>>>(dA, dec_w, dec_b, out_w, out_b, (float*)d_out);
}

// round 6
// speedup vs baseline: 1.2626x; 1.0002x over previous
#include <cuda_runtime.h>
#include <math.h>

#define BB   4
#define TT0  128
#define WD   128
#define EB   16
#define LL   2048
#define ODIM 24
#define TF   122

// ---------------- scratch (no allocations allowed) ----------------
__device__ float g_bufA[BB*WD*TT0*EB];   // 4 MB
__device__ float g_bufB[BB*WD*TT0*EB];   // 4 MB
__device__ float g_Mt[2*WD*WD];          // Mt[m*128+n] = (Wq Wk^T)[n][m]
__device__ float g_uu[2*WD];             // u = Wq bk
__device__ float g_ww[2*WD];             // w = Wk bq
__device__ float g_cc[2];                // c = bq . bk
__device__ float g_yv[BB*126*WD];        // per-(b,t) y vectors
__device__ float g_zz[BB*126*EB*WD];     // Z[bt][f][n]  ~4.1 MB

// ---------------- f32x2 packed helpers ----------------
__device__ __forceinline__ unsigned long long fma2(unsigned long long a,
                                                   unsigned long long b,
                                                   unsigned long long c) {
    unsigned long long d;
    asm("fma.rn.f32x2 %0, %1, %2, %3;" : "=l"(d) : "l"(a), "l"(b), "l"(c));
    return d;
}
__device__ __forceinline__ unsigned long long pack2(float v) {
    unsigned long long r;
    asm("mov.b64 %0, {%1, %1};" : "=l"(r) : "f"(v));
    return r;
}
__device__ __forceinline__ void unpack2(unsigned long long v, float& lo, float& hi) {
    asm("mov.b64 {%0, %1}, %2;" : "=f"(lo), "=f"(hi) : "l"(v));
}

// ---------------- embed: x_in -> (B,N,T,E) ----------------
__global__ void k_embed(const float* __restrict__ x_in,
                        const float* __restrict__ emb_w,
                        const float* __restrict__ emb_b,
                        float* __restrict__ out) {
    int idx = blockIdx.x*blockDim.x + threadIdx.x;   // over B*T*N
    if (idx >= BB*TT0*WD) return;
    int n = idx & 127;
    int t = (idx >> 7) & 127;
    int b = idx >> 14;
    const float* xi = x_in + (b*TT0 + t)*131;
    float v  = xi[n];
    float f0 = xi[128], f1 = xi[129], f2 = xi[130];
    float* o = out + ((b*WD + n)*TT0 + t)*EB;
    #pragma unroll
    for (int e = 0; e < EB; e++)
        o[e] = v*emb_w[e] + f0*emb_w[16+e] + f1*emb_w[32+e] + f2*emb_w[48+e] + emb_b[e];
}

// ---------------- precompute Mt[m*128+n] = sum_l Wq[n,l]*Wk[m,l], both layers ----------------
__global__ void k_mt(const float* __restrict__ Wq0, const float* __restrict__ Wk0,
                     const float* __restrict__ Wq1, const float* __restrict__ Wk1,
                     float* __restrict__ Mt) {
    __shared__ float Aq[16][65], Ak[16][65];
    int ly = blockIdx.y;
    const float* Wq = ly ? Wq1 : Wq0;
    const float* Wk = ly ? Wk1 : Wk0;
    float* Mto = Mt + ly*WD*WD;
    int bm = blockIdx.x >> 3, bn = blockIdx.x & 7;
    int m0 = bm*16, n0 = bn*16;
    int ty = threadIdx.x >> 4, tx = threadIdx.x & 15;  // ty -> m, tx -> n
    float acc = 0.f;
    for (int l0 = 0; l0 < LL; l0 += 64) {
        #pragma unroll
        for (int r = 0; r < 4; r++) {
            int idx = threadIdx.x + r*256;
            int row = idx >> 6, col = idx & 63;
            Aq[row][col] = Wq[(n0+row)*LL + l0 + col];
            Ak[row][col] = Wk[(m0+row)*LL + l0 + col];
        }
        __syncthreads();
        #pragma unroll
        for (int lc = 0; lc < 64; lc++)
            acc += Ak[ty][lc]*Aq[tx][lc];
        __syncthreads();
    }
    Mto[(m0+ty)*WD + (n0+tx)] = acc;
}

// ---------------- precompute u, w, c (both layers) ----------------
__global__ void k_uw(const float* __restrict__ Wq0, const float* __restrict__ Wk0,
                     const float* __restrict__ bq0, const float* __restrict__ bk0,
                     const float* __restrict__ Wq1, const float* __restrict__ Wk1,
                     const float* __restrict__ bq1, const float* __restrict__ bk1,
                     float* __restrict__ u, float* __restrict__ w, float* __restrict__ cp) {
    int ly = blockIdx.y;
    const float* Wq = ly ? Wq1 : Wq0;
    const float* Wk = ly ? Wk1 : Wk0;
    const float* bq = ly ? bq1 : bq0;
    const float* bk = ly ? bk1 : bk0;
    int n = blockIdx.x;
    __shared__ float su[256], sw[256], sc[256];
    float pu = 0.f, pw = 0.f, pc = 0.f;
    for (int l = threadIdx.x; l < LL; l += 256) {
        float bkl = bk[l], bql = bq[l];
        pu += Wq[n*LL + l]*bkl;
        pw += Wk[n*LL + l]*bql;
        if (n == 0) pc += bql*bkl;
    }
    su[threadIdx.x] = pu; sw[threadIdx.x] = pw; sc[threadIdx.x] = pc;
    __syncthreads();
    for (int s = 128; s > 0; s >>= 1) {
        if (threadIdx.x < s) {
            su[threadIdx.x] += su[threadIdx.x + s];
            sw[threadIdx.x] += sw[threadIdx.x + s];
            sc[threadIdx.x] += sc[threadIdx.x + s];
        }
        __syncthreads();
    }
    if (threadIdx.x == 0) {
        u[ly*WD + n] = su[0]; w[ly*WD + n] = sw[0];
        if (n == 0) cp[ly] = sc[0];
    }
}

// ---------------- gated conv v4: e-half split for occupancy ----------------
// Block: 128 thr = 64 ol x 2 eq-locals; handles (o-half, e-half) of one time tile.
template<int TIN, int TOUT, int D>
__global__ void k_gated4(const float* __restrict__ X,
                         const float* __restrict__ wf, const float* __restrict__ bf,
                         const float* __restrict__ wg, const float* __restrict__ bg,
                         float* __restrict__ Y) {
    constexpr int TT = 4;
    constexpr int WIDTH = TT + D;
    constexpr int C = 16;          // i-chunk
    constexpr int WROW = 65;       // padded row for [ict][o_local]
    extern __shared__ float sm[];
    float* Xs  = sm;                          // [128][WIDTH][8]
    float* Wfs = sm + WD*WIDTH*8;             // [2*C][WROW]
    float* Wgs = Wfs + 2*C*WROW;              // [2*C][WROW]

    const int ntile = (TOUT + TT - 1)/TT;
    int bid = blockIdx.x;
    int be  = bid & 1;                        // e-half
    int bo  = (bid >> 1) & 1;                 // o-half
    int bt  = bid >> 2;
    int b   = bt / ntile;
    int t0  = (bt % ntile)*TT;
    int tid = threadIdx.x;                    // 128
    int ol  = tid >> 1;                       // 0..63
    int o   = bo*64 + ol;
    int eql = tid & 1;                        // quad within e-half
    int e0  = be*8;

    // cooperative X tile load: [i][w][8e], float4 granularity (2 quads per (i,w))
    for (int idx = tid; idx < WD*WIDTH*2; idx += 128) {
        int q = idx & 1;
        int w = (idx >> 1) % WIDTH;
        int i = idx / (2*WIDTH);
        int t = t0 + w;
        float4 v = make_float4(0.f, 0.f, 0.f, 0.f);
        if (t < TIN) v = *(const float4*)(X + ((b*WD + i)*TIN + t)*16 + e0 + q*4);
        *(float4*)(Xs + (i*WIDTH + w)*8 + q*4) = v;
    }

    unsigned long long fa[TT][2], ga[TT][2];
    #pragma unroll
    for (int t = 0; t < TT; t++) { fa[t][0]=0ull; fa[t][1]=0ull; ga[t][0]=0ull; ga[t][1]=0ull; }

    for (int i0 = 0; i0 < WD; i0 += C) {
        __syncthreads();   // also covers initial X load; protects Wfs reuse
        // stage weights chunk for this o-half
        for (int idx = tid; idx < 64*2*C; idx += 128) {
            int o2 = idx >> 5, ict = idx & 31;
            Wfs[ict*WROW + o2] = wf[(bo*64 + o2)*(WD*2) + i0*2 + ict];
            Wgs[ict*WROW + o2] = wg[(bo*64 + o2)*(WD*2) + i0*2 + ict];
        }
        __syncthreads();
        #pragma unroll
        for (int ic = 0; ic < C; ic++) {
            int i = i0 + ic;
            unsigned long long pf0 = pack2(Wfs[(ic*2+0)*WROW + ol]);
            unsigned long long pf1 = pack2(Wfs[(ic*2+1)*WROW + ol]);
            unsigned long long pg0 = pack2(Wgs[(ic*2+0)*WROW + ol]);
            unsigned long long pg1 = pack2(Wgs[(ic*2+1)*WROW + ol]);
            unsigned long long x[WIDTH][2];
            #pragma unroll
            for (int w = 0; w < WIDTH; w++) {
                ulonglong2 v = *(const ulonglong2*)(Xs + (i*WIDTH + w)*8 + eql*4);
                x[w][0] = v.x; x[w][1] = v.y;
            }
            #pragma unroll
            for (int t = 0; t < TT; t++) {
                fa[t][0] = fma2(pf0, x[t][0],   fa[t][0]);
                fa[t][1] = fma2(pf0, x[t][1],   fa[t][1]);
                fa[t][0] = fma2(pf1, x[t+D][0], fa[t][0]);
                fa[t][1] = fma2(pf1, x[t+D][1], fa[t][1]);
                ga[t][0] = fma2(pg0, x[t][0],   ga[t][0]);
                ga[t][1] = fma2(pg0, x[t][1],   ga[t][1]);
                ga[t][0] = fma2(pg1, x[t+D][0], ga[t][0]);
                ga[t][1] = fma2(pg1, x[t+D][1], ga[t][1]);
            }
        }
    }

    float bfo = bf[o], bgo = bg[o];
    #pragma unroll
    for (int t = 0; t < TT; t++) {
        int tt = t0 + t;
        if (tt < TOUT) {
            float f0,f1,f2,f3, g0,g1,g2,g3;
            unpack2(fa[t][0], f0, f1); unpack2(fa[t][1], f2, f3);
            unpack2(ga[t][0], g0, g1); unpack2(ga[t][1], g2, g3);
            float4 r;
            r.x = tanhf(f0 + bfo)*(1.f/(1.f + expf(-(g0 + bgo))));
            r.y = tanhf(f1 + bfo)*(1.f/(1.f + expf(-(g1 + bgo))));
            r.z = tanhf(f2 + bfo)*(1.f/(1.f + expf(-(g2 + bgo))));
            r.w = tanhf(f3 + bfo)*(1.f/(1.f + expf(-(g3 + bgo))));
            *(float4*)(Y + ((b*WD + o)*TOUT + tt)*16 + e0 + eql*4) = r;
        }
    }
}

// ---------------- gated residual v2: tiled smem GEMM ----------------
template<int TIN, int TOUT>
__global__ void k_res2(const float* __restrict__ X, const float* __restrict__ ws,
                       const float* __restrict__ bs, float* __restrict__ Y) {
    constexpr int RPB = 64;
    constexpr int KC  = 32;
    __shared__ float As[KC][RPB];       // [t][row]
    __shared__ float Ws[KC][132];       // [t][s], 16B-aligned rows
    int b  = blockIdx.x >> 5;
    int r0 = (blockIdx.x & 31)*RPB;
    int tid = threadIdx.x;              // 256
    int rq = tid >> 4;                  // 0..15 -> rows rq*4..+3
    int sg = tid & 15;                  // s = sg*8 .. +7

    unsigned long long acc[4][4];
    #pragma unroll
    for (int r = 0; r < 4; r++)
        #pragma unroll
        for (int j = 0; j < 4; j++) acc[r][j] = 0ull;

    for (int t0 = 0; t0 < TIN; t0 += KC) {
        __syncthreads();
        #pragma unroll
        for (int j = 0; j < (RPB*KC)/256; j++) {
            int idx = tid + j*256;
            int row = idx & (RPB-1);
            int t = idx >> 6;
            int rr = r0 + row;
            int n = rr >> 4, e = rr & 15;
            int tg = t0 + t;
            As[t][row] = (tg < TIN) ? X[((b*WD + n)*TIN + tg)*EB + e] : 0.f;
        }
        #pragma unroll
        for (int j = 0; j < (KC*128)/256; j++) {
            int idx = tid + j*256;
            int s = idx & 127;
            int t = idx >> 7;
            int tg = t0 + t;
            Ws[t][s] = (tg < TIN && s < TOUT) ? ws[tg*TOUT + s] : 0.f;
        }
        __syncthreads();
        #pragma unroll
        for (int t = 0; t < KC; t++) {
            float4 w0 = *(const float4*)(&Ws[t][sg*8]);
            float4 w1 = *(const float4*)(&Ws[t][sg*8 + 4]);
            unsigned long long wv[4];
            wv[0] = ((unsigned long long)__float_as_uint(w0.y) << 32) | __float_as_uint(w0.x);
            wv[1] = ((unsigned long long)__float_as_uint(w0.w) << 32) | __float_as_uint(w0.z);
            wv[2] = ((unsigned long long)__float_as_uint(w1.y) << 32) | __float_as_uint(w1.x);
            wv[3] = ((unsigned long long)__float_as_uint(w1.w) << 32) | __float_as_uint(w1.z);
            #pragma unroll
            for (int r = 0; r < 4; r++) {
                unsigned long long av = pack2(As[t][rq*4 + r]);
                #pragma unroll
                for (int j = 0; j < 4; j++)
                    acc[r][j] = fma2(av, wv[j], acc[r][j]);
            }
        }
    }
    #pragma unroll
    for (int r = 0; r < 4; r++) {
        int rr = r0 + rq*4 + r;
        int n = rr >> 4, e = rr & 15;
        float* yp = Y + ((size_t)(b*WD + n)*TOUT)*EB + e;
        #pragma unroll
        for (int j = 0; j < 4; j++) {
            float lo, hi; unpack2(acc[r][j], lo, hi);
            int s0 = sg*8 + j*2;
            if (s0 < TOUT)   yp[s0*EB]       += lo + bs[s0];
            if (s0+1 < TOUT) yp[(s0+1)*EB]   += hi + bs[s0+1];
        }
    }
}

// ---------------- batched Z GEMM: Z[j,n] = sum_m Mt[m,n] * X[b,m,t,f], j=(bt)*16+f ----
template<int T>
__global__ void k_zgemm(const float* __restrict__ Xv, const float* __restrict__ Mt,
                        float* __restrict__ Zall) {
    constexpr int JT = 64, KC = 32;
    constexpr int J  = BB*T*EB;
    constexpr int T16 = T*16;
    __shared__ float Ms[KC][WD];      // [k][n]
    __shared__ float Bs[KC][JT];      // [k][jl]
    int j0 = blockIdx.x*JT;
    int tid = threadIdx.x;            // 256
    int nq = tid & 15;                // n = nq*8
    int jq = tid >> 4;                // jl = jq*4..+3
    unsigned long long acc[4][4];
    #pragma unroll
    for (int r = 0; r < 4; r++)
        #pragma unroll
        for (int c = 0; c < 4; c++) acc[r][c] = 0ull;

    for (int m0 = 0; m0 < WD; m0 += KC) {
        __syncthreads();
        #pragma unroll
        for (int rep = 0; rep < (KC*WD)/256; rep++) {
            int idx = tid + rep*256;
            int k = idx >> 7, n = idx & 127;
            Ms[k][n] = Mt[(m0 + k)*WD + n];
        }
        #pragma unroll
        for (int rep = 0; rep < (KC*JT)/256; rep++) {
            int idx = tid + rep*256;
            int k = idx >> 6, jl = idx & 63;
            int jg = j0 + jl;
            float v = 0.f;
            if (jg < J) {
                int b = jg / T16;
                v = Xv[jg + (b*(WD-1) + m0 + k)*T16];
            }
            Bs[k][jl] = v;
        }
        __syncthreads();
        #pragma unroll
        for (int k = 0; k < KC; k++) {
            ulonglong2 m01 = *(const ulonglong2*)(&Ms[k][nq*8]);
            ulonglong2 m23 = *(const ulonglong2*)(&Ms[k][nq*8 + 4]);
            unsigned long long mv0 = m01.x, mv1 = m01.y, mv2 = m23.x, mv3 = m23.y;
            float4 bj = *(const float4*)(&Bs[k][jq*4]);
            unsigned long long bv[4] = {pack2(bj.x), pack2(bj.y), pack2(bj.z), pack2(bj.w)};
            #pragma unroll
            for (int c = 0; c < 4; c++) {
                acc[0][c] = fma2(mv0, bv[c], acc[0][c]);
                acc[1][c] = fma2(mv1, bv[c], acc[1][c]);
                acc[2][c] = fma2(mv2, bv[c], acc[2][c]);
                acc[3][c] = fma2(mv3, bv[c], acc[3][c]);
            }
        }
    }
    #pragma unroll
    for (int c = 0; c < 4; c++) {
        int jg = j0 + jq*4 + c;
        if (jg < J) {
            float* op = Zall + (size_t)jg*WD + nq*8;
            float4 o0, o1;
            unpack2(acc[0][c], o0.x, o0.y);
            unpack2(acc[1][c], o0.z, o0.w);
            unpack2(acc[2][c], o1.x, o1.y);
            unpack2(acc[3][c], o1.z, o1.w);
            *(float4*)(op)     = o0;
            *(float4*)(op + 4) = o1;
        }
    }
}

// ---------------- attention softmax + ybar (Z precomputed) ----------------
template<int T>
__global__ void k_attn_sm(const float* __restrict__ X, const float* __restrict__ Zall,
                          const float* __restrict__ u, const float* __restrict__ w,
                          const float* __restrict__ cptr, float* __restrict__ yout) {
    __shared__ __align__(16) float Xs[WD*EB];   // [n][e]
    __shared__ float Zs[EB][WD+5];              // [f][n] pad 133 (conflict-free)
    __shared__ float Ss[EB][EB+1];
    __shared__ float uev[EB], wfv[EB], abar[EB];
    int bt = blockIdx.x;
    int b = bt / T, t = bt % T;
    int tid = threadIdx.x;                      // 256
    for (int idx = tid; idx < WD*EB; idx += 256) {
        int n = idx >> 4, e = idx & 15;
        Xs[idx] = X[((b*WD + n)*T + t)*EB + e];
    }
    for (int idx = tid; idx < EB*WD; idx += 256) {
        int f = idx >> 7, n = idx & 127;
        Zs[f][n] = Zall[(size_t)bt*(EB*WD) + idx];
    }
    __syncthreads();
    if (tid < 16) {
        float a = 0.f;
        for (int n = 0; n < WD; n++) a += Xs[n*16 + tid]*u[n];
        uev[tid] = a;
    } else if (tid < 32) {
        int f = tid - 16;
        float a = 0.f;
        for (int n = 0; n < WD; n++) a += Xs[n*16 + f]*w[n];
        wfv[f] = a;
    }
    __syncthreads();
    {
        int e = tid >> 4, f = tid & 15;
        float acc = 0.f;
        #pragma unroll 4
        for (int n = 0; n < WD; n++)
            acc += Xs[n*16 + e]*Zs[f][n];
        const float scale = 0.022097086912079608f; // 1/sqrt(2048)
        Ss[e][f] = (acc + uev[e] + wfv[f] + cptr[0])*scale;
    }
    __syncthreads();
    if (tid < 16) {
        int e = tid;
        float mx = -1e30f;
        #pragma unroll
        for (int f = 0; f < 16; f++) mx = fmaxf(mx, Ss[e][f]);
        float ex[16]; float sum = 0.f;
        #pragma unroll
        for (int f = 0; f < 16; f++) { ex[f] = expf(Ss[e][f] - mx); sum += ex[f]; }
        float inv = 1.f/sum;
        #pragma unroll
        for (int f = 0; f < 16; f++) Ss[e][f] = ex[f]*inv;
    }
    __syncthreads();
    if (tid < 16) {
        int f = tid;
        float a = 0.f;
        #pragma unroll
        for (int e = 0; e < 16; e++) a += Ss[e][f];
        abar[f] = a*(1.f/16.f);
    }
    __syncthreads();
    if (tid < 128) {
        int n = tid;
        float a = 0.f;
        #pragma unroll
        for (int f = 0; f < 16; f++) a += Xs[n*16 + f]*abar[f];
        yout[bt*WD + n] = a;
    }
}

// ---------------- attention out: Y = X + y @ Wv + bv ----------------
template<int T>
__global__ void k_attn_out(const float* __restrict__ Xin, const float* __restrict__ yv,
                           const float* __restrict__ Wv, const float* __restrict__ bv,
                           float* __restrict__ Yout) {
    __shared__ float ys[64][WD];
    const int BT = BB*T;
    int bt0 = blockIdx.y*64;
    int l = blockIdx.x*128 + (threadIdx.x & 127);
    int half = threadIdx.x >> 7;
    for (int idx = threadIdx.x; idx < 64*WD; idx += 256) {
        int r = idx >> 7, m = idx & 127;
        int bt = bt0 + r;
        ys[r][m] = (bt < BT) ? yv[bt*WD + m] : 0.f;
    }
    __syncthreads();
    float acc[32];
    #pragma unroll
    for (int j = 0; j < 32; j++) acc[j] = 0.f;
    for (int m = 0; m < WD; m++) {
        float wvv = Wv[m*LL + l];
        #pragma unroll
        for (int j = 0; j < 32; j++) acc[j] += ys[half*32 + j][m]*wvv;
    }
    float bvl = bv[l];
    int n = l >> 4, e = l & 15;
    #pragma unroll
    for (int j = 0; j < 32; j++) {
        int bt = bt0 + half*32 + j;
        if (bt < BT) {
            int b = bt / T, t = bt % T;
            int idx = ((b*WD + n)*T + t)*EB + e;
            Yout[idx] = Xin[idx] + acc[j] + bvl;
        }
    }
}

// ---------------- decode + time-mix output ----------------
__global__ void k_decode(const float* __restrict__ X, const float* __restrict__ dec_w,
                         const float* __restrict__ dec_b, const float* __restrict__ out_w,
                         const float* __restrict__ out_b, float* __restrict__ out) {
    __shared__ float sy[TF];
    int b = blockIdx.x >> 7, n = blockIdx.x & 127;
    int t = threadIdx.x;
    if (t < TF) {
        const float* xp = X + ((size_t)(b*WD + n)*TF + t)*EB;
        float a = dec_b[n];
        #pragma unroll
        for (int e = 0; e < EB; e++) a += xp[e]*dec_w[n*EB + e];
        sy[t] = a;
    }
    __syncthreads();
    if (t < ODIM) {
        float a = out_b[t];
        for (int tt = 0; tt < TF; tt++) a += sy[tt]*out_w[tt*ODIM + t];
        out[(b*ODIM + t)*WD + n] = a;
    }
}

// ---------------- launcher ----------------
extern "C" void kernel_launch(void* const* d_in, const int* in_sizes, int n_in,
                              void* d_out, int out_size) {
    const float* x_in  = (const float*)d_in[0];
    const float* emb_w = (const float*)d_in[1];
    const float* emb_b = (const float*)d_in[2];
    const float* g0_wf = (const float*)d_in[3];
    const float* g0_bf = (const float*)d_in[4];
    const float* g0_wg = (const float*)d_in[5];
    const float* g0_bg = (const float*)d_in[6];
    const float* g0_ws = (const float*)d_in[7];
    const float* g0_bs = (const float*)d_in[8];
    const float* a0_wq = (const float*)d_in[9];
    const float* a0_bq = (const float*)d_in[10];
    const float* a0_wk = (const float*)d_in[11];
    const float* a0_bk = (const float*)d_in[12];
    const float* a0_wv = (const float*)d_in[13];
    const float* a0_bv = (const float*)d_in[14];
    const float* g1_wf = (const float*)d_in[15];
    const float* g1_bf = (const float*)d_in[16];
    const float* g1_wg = (const float*)d_in[17];
    const float* g1_bg = (const float*)d_in[18];
    const float* g1_ws = (const float*)d_in[19];
    const float* g1_bs = (const float*)d_in[20];
    const float* a1_wq = (const float*)d_in[21];
    const float* a1_bq = (const float*)d_in[22];
    const float* a1_wk = (const float*)d_in[23];
    const float* a1_bk = (const float*)d_in[24];
    const float* a1_wv = (const float*)d_in[25];
    const float* a1_bv = (const float*)d_in[26];
    const float* dec_w = (const float*)d_in[27];
    const float* dec_b = (const float*)d_in[28];
    const float* out_w = (const float*)d_in[29];
    const float* out_b = (const float*)d_in[30];

    float *dA, *dB, *dMt, *dU, *dW, *dC, *dY, *dZ;
    cudaGetSymbolAddress((void**)&dA,  g_bufA);
    cudaGetSymbolAddress((void**)&dB,  g_bufB);
    cudaGetSymbolAddress((void**)&dMt, g_Mt);
    cudaGetSymbolAddress((void**)&dU,  g_uu);
    cudaGetSymbolAddress((void**)&dW,  g_ww);
    cudaGetSymbolAddress((void**)&dC,  g_cc);
    cudaGetSymbolAddress((void**)&dY,  g_yv);
    cudaGetSymbolAddress((void**)&dZ,  g_zz);

    // smem sizes for gated4 (e-half): X [128][W][8] + weights 2*[32][65]
    const int SMEM_G0 = (WD*6*8 + 2*2*16*65)*4;    // 24576 + 16640 = 41216
    const int SMEM_G1 = (WD*8*8 + 2*2*16*65)*4;    // 32768 + 16640 = 49408
    cudaFuncSetAttribute(k_gated4<128,126,2>, cudaFuncAttributeMaxDynamicSharedMemorySize, SMEM_G0);
    cudaFuncSetAttribute(k_gated4<126,122,4>, cudaFuncAttributeMaxDynamicSharedMemorySize, SMEM_G1);

    // embed + attention precompute (merged launches)
    k_embed<<<(BB*TT0*WD + 255)/256, 256>>>(x_in, emb_w, emb_b, dA);
    k_mt<<<dim3(64,2), 256>>>(a0_wq, a0_wk, a1_wq, a1_wk, dMt);
    k_uw<<<dim3(128,2), 256>>>(a0_wq, a0_wk, a0_bq, a0_bk,
                               a1_wq, a1_wk, a1_bq, a1_bk, dU, dW, dC);

    // layer 0: gated (TIN=128 -> 126, d=2), attention T=126
    {
        const int ntile = (126 + 3)/4;  // 32
        k_gated4<128,126,2><<<BB*ntile*4, 128, SMEM_G0>>>(dA, g0_wf, g0_bf, g0_wg, g0_bg, dB);
        k_res2<128,126><<<BB*32, 256>>>(dA, g0_ws, g0_bs, dB);
        k_zgemm<126><<<(BB*126*EB + 63)/64, 256>>>(dB, dMt, dZ);
        k_attn_sm<126><<<BB*126, 256>>>(dB, dZ, dU, dW, dC, dY);
        k_attn_out<126><<<dim3(16, (BB*126 + 63)/64), 256>>>(dB, dY, a0_wv, a0_bv, dA);
    }

    // layer 1: gated (TIN=126 -> 122, d=4), attention T=122
    {
        const int ntile = (122 + 3)/4;  // 31
        k_gated4<126,122,4><<<BB*ntile*4, 128, SMEM_G1>>>(dA, g1_wf, g1_bf, g1_wg, g1_bg, dB);
        k_res2<126,122><<<BB*32, 256>>>(dA, g1_ws, g1_bs, dB);
        k_zgemm<122><<<(BB*122*EB + 63)/64, 256>>>(dB, dMt + WD*WD, dZ);
        k_attn_sm<122><<<BB*122, 256>>>(dB, dZ, dU + WD, dW + WD, dC + 1, dY);
        k_attn_out<122><<<dim3(16, (BB*122 + 63)/64), 256>>>(dB, dY, a1_wv, a1_bv, dA);
    }

    // decode
    k_decode<<<BB*WD, 128>>>(dA, dec_w, dec_b, out_w, out_b, (float*)d_out);
}